// round 1
// baseline (speedup 1.0000x reference)
#include <cuda_runtime.h>
#include <cstdint>

// Problem dims
#define Bq   4
#define Sq   2048
#define Dq   1024
#define Hq   16
#define HDq  64
#define Mq   (Bq*Sq)      // 8192 rows

// Scratch (device globals: allocation-free per harness rules)
__device__ float g_rscale[Mq];
__device__ float g_q[(size_t)Mq*Dq];
__device__ float g_k[(size_t)Mq*Dq];
__device__ float g_v[(size_t)Mq*Dq];
__device__ float g_ctx[(size_t)Mq*Dq];

// ---------------------------------------------------------------------------
// Kernel 1: RMS norm row scale: rscale[r] = rsqrt(mean(x^2) + 1e-6)
// ---------------------------------------------------------------------------
__global__ __launch_bounds__(256) void rms_kernel(const float* __restrict__ x) {
    int row = blockIdx.x;
    const float* xr = x + (size_t)row * Dq;
    float s = 0.f;
    for (int i = threadIdx.x; i < Dq; i += 256) {
        float v = xr[i];
        s += v * v;
    }
    __shared__ float red[8];
    #pragma unroll
    for (int o = 16; o > 0; o >>= 1) s += __shfl_xor_sync(0xffffffffu, s, o);
    if ((threadIdx.x & 31) == 0) red[threadIdx.x >> 5] = s;
    __syncthreads();
    if (threadIdx.x == 0) {
        float t = 0.f;
        #pragma unroll
        for (int i = 0; i < 8; i++) t += red[i];
        g_rscale[row] = rsqrtf(t * (1.0f / (float)Dq) + 1e-6f);
    }
}

// ---------------------------------------------------------------------------
// Kernel 2: fused QKV GEMM.  C = (diag(rscale) * X * diag(lnw)) @ W
// blockIdx.z selects (wq->g_q, wk->g_k, wv->g_v)
// Tiles: BM=BN=64, BK=16, 256 threads, 4x4 per-thread microtile.
// ---------------------------------------------------------------------------
__global__ __launch_bounds__(256) void gemm_qkv_kernel(
    const float* __restrict__ x,
    const float* __restrict__ wq, const float* __restrict__ wk,
    const float* __restrict__ wv, const float* __restrict__ lnw)
{
    const float* W = (blockIdx.z == 0) ? wq : (blockIdx.z == 1) ? wk : wv;
    float* C       = (blockIdx.z == 0) ? g_q : (blockIdx.z == 1) ? g_k : g_v;

    __shared__ float As[64][17];   // +1 pad: 2-way max conflict on reads
    __shared__ float Bs[16][64];

    int tid = threadIdx.x;
    int tx = tid & 15, ty = tid >> 4;
    int row0 = blockIdx.y << 6, col0 = blockIdx.x << 6;

    float acc[4][4] = {};

    for (int k0 = 0; k0 < Dq; k0 += 16) {
        #pragma unroll
        for (int u = 0; u < 4; u++) {
            int idx = tid + u * 256;          // 0..1023
            int r = idx >> 4, c = idx & 15;   // A: 64x16
            As[r][c] = x[(size_t)(row0 + r) * Dq + k0 + c]
                       * g_rscale[row0 + r] * lnw[k0 + c];
            int r2 = idx >> 6, c2 = idx & 63; // B: 16x64
            Bs[r2][c2] = W[(size_t)(k0 + r2) * Dq + col0 + c2];
        }
        __syncthreads();
        #pragma unroll
        for (int kk = 0; kk < 16; kk++) {
            float a[4], b[4];
            #pragma unroll
            for (int i = 0; i < 4; i++) a[i] = As[ty * 4 + i][kk];
            #pragma unroll
            for (int j = 0; j < 4; j++) b[j] = Bs[kk][tx * 4 + j];
            #pragma unroll
            for (int i = 0; i < 4; i++)
                #pragma unroll
                for (int j = 0; j < 4; j++)
                    acc[i][j] += a[i] * b[j];
        }
        __syncthreads();
    }
    #pragma unroll
    for (int i = 0; i < 4; i++)
        #pragma unroll
        for (int j = 0; j < 4; j++)
            C[(size_t)(row0 + ty * 4 + i) * Dq + col0 + tx * 4 + j] = acc[i][j];
}

// ---------------------------------------------------------------------------
// Kernel 3: flash attention with T5 relative-position bias (no mask, no 1/sqrt(d))
// One block per (b,h, 64-query tile). 256 threads, 4x4 microtiles.
// ---------------------------------------------------------------------------
__global__ __launch_bounds__(256) void flash_kernel(const float* __restrict__ rel_emb)
{
    extern __shared__ float sm[];
    float (*Qs)[65]  = (float(*)[65])sm;                       // 64x65
    float (*KsT)[65] = (float(*)[65])(sm + 64 * 65);           // KsT[d][key] 64x65
    float (*Vs)[64]  = (float(*)[64])(sm + 2 * 64 * 65);       // 64x64
    float (*Ps)[65]  = (float(*)[65])(sm + 2 * 64 * 65 + 64 * 64); // 64x65
    __shared__ float bias_tab[32];

    int q0 = blockIdx.x << 6;
    int bh = blockIdx.y;
    int b = bh >> 4, h = bh & 15;
    int tid = threadIdx.x;
    int tx = tid & 15, ty = tid >> 4;

    if (tid < 32) bias_tab[tid] = rel_emb[tid * Hq + h];

    const size_t base = ((size_t)b * Sq) * (Hq * HDq) + (size_t)h * HDq;

    // Q tile (rows contiguous over d)
    for (int i = tid; i < 64 * 64; i += 256) {
        int r = i >> 6, d = i & 63;
        Qs[r][d] = g_q[base + (size_t)(q0 + r) * (Hq * HDq) + d];
    }

    const float NEG_INF = __int_as_float(0xff800000u);
    float m[4], l[4], o[4][4];
    #pragma unroll
    for (int i = 0; i < 4; i++) {
        m[i] = NEG_INF; l[i] = 0.f;
        #pragma unroll
        for (int j = 0; j < 4; j++) o[i][j] = 0.f;
    }

    for (int k0 = 0; k0 < Sq; k0 += 64) {
        __syncthreads();   // protect KsT/Vs (prev PV done) + Q-load on first iter
        for (int i = tid; i < 64 * 64; i += 256) {
            int r = i >> 6, d = i & 63;
            float kv = g_k[base + (size_t)(k0 + r) * (Hq * HDq) + d];
            KsT[d][r] = kv;
            Vs[r][d]  = g_v[base + (size_t)(k0 + r) * (Hq * HDq) + d];
        }
        __syncthreads();

        // S = Q K^T  (4x4 microtile per thread)
        float s[4][4] = {};
        #pragma unroll
        for (int kk = 0; kk < 64; kk++) {
            float a[4], bb[4];
            #pragma unroll
            for (int i = 0; i < 4; i++) a[i] = Qs[ty * 4 + i][kk];
            #pragma unroll
            for (int j = 0; j < 4; j++) bb[j] = KsT[kk][tx * 4 + j];
            #pragma unroll
            for (int i = 0; i < 4; i++)
                #pragma unroll
                for (int j = 0; j < 4; j++)
                    s[i][j] += a[i] * bb[j];
        }

        // + relative position bias
        #pragma unroll
        for (int i = 0; i < 4; i++) {
            int q = q0 + ty * 4 + i;
            #pragma unroll
            for (int j = 0; j < 4; j++) {
                int kpos = k0 + tx * 4 + j;
                int rp = q - kpos; if (rp < 0) rp = 0;
                int bk;
                if (rp < 16) {
                    bk = rp;
                } else {
                    bk = 16 + (int)(__logf((float)rp * 0.0625f) * 7.6944086f);
                    if (bk > 31) bk = 31;
                }
                s[i][j] += bias_tab[bk];
            }
        }

        // online softmax (row groups of 16 lanes: fixed ty -> lanes tx 0..15)
        #pragma unroll
        for (int i = 0; i < 4; i++) {
            float mx = s[i][0];
            #pragma unroll
            for (int j = 1; j < 4; j++) mx = fmaxf(mx, s[i][j]);
            #pragma unroll
            for (int off = 8; off > 0; off >>= 1)
                mx = fmaxf(mx, __shfl_xor_sync(0xffffffffu, mx, off));
            float mn = fmaxf(m[i], mx);
            float alpha = __expf(m[i] - mn);
            float rs = 0.f;
            #pragma unroll
            for (int j = 0; j < 4; j++) {
                float p = __expf(s[i][j] - mn);
                s[i][j] = p;
                rs += p;
            }
            #pragma unroll
            for (int off = 8; off > 0; off >>= 1)
                rs += __shfl_xor_sync(0xffffffffu, rs, off);
            l[i] = l[i] * alpha + rs;
            m[i] = mn;
            #pragma unroll
            for (int j = 0; j < 4; j++) o[i][j] *= alpha;
            #pragma unroll
            for (int j = 0; j < 4; j++) Ps[ty * 4 + i][tx * 4 + j] = s[i][j];
        }
        __syncthreads();

        // O += P V  (thread owns rows 4ty.., dims 4tx..)
        #pragma unroll
        for (int kk = 0; kk < 64; kk++) {
            float a[4], bv[4];
            #pragma unroll
            for (int i = 0; i < 4; i++) a[i] = Ps[ty * 4 + i][kk];
            #pragma unroll
            for (int j = 0; j < 4; j++) bv[j] = Vs[kk][tx * 4 + j];
            #pragma unroll
            for (int i = 0; i < 4; i++)
                #pragma unroll
                for (int j = 0; j < 4; j++)
                    o[i][j] += a[i] * bv[j];
        }
    }

    #pragma unroll
    for (int i = 0; i < 4; i++) {
        float inv = 1.0f / l[i];
        #pragma unroll
        for (int j = 0; j < 4; j++)
            g_ctx[base + (size_t)(q0 + ty * 4 + i) * (Hq * HDq) + tx * 4 + j] =
                o[i][j] * inv;
    }
}

// ---------------------------------------------------------------------------
// Kernel 4: output GEMM + residual.  out = origin + ctx @ wo
// ---------------------------------------------------------------------------
__global__ __launch_bounds__(256) void gemm_out_kernel(
    const float* __restrict__ wo, const float* __restrict__ origin,
    float* __restrict__ out)
{
    __shared__ float As[64][17];
    __shared__ float Bs[16][64];

    int tid = threadIdx.x;
    int tx = tid & 15, ty = tid >> 4;
    int row0 = blockIdx.y << 6, col0 = blockIdx.x << 6;

    float acc[4][4] = {};

    for (int k0 = 0; k0 < Dq; k0 += 16) {
        #pragma unroll
        for (int u = 0; u < 4; u++) {
            int idx = tid + u * 256;
            int r = idx >> 4, c = idx & 15;
            As[r][c] = g_ctx[(size_t)(row0 + r) * Dq + k0 + c];
            int r2 = idx >> 6, c2 = idx & 63;
            Bs[r2][c2] = wo[(size_t)(k0 + r2) * Dq + col0 + c2];
        }
        __syncthreads();
        #pragma unroll
        for (int kk = 0; kk < 16; kk++) {
            float a[4], b[4];
            #pragma unroll
            for (int i = 0; i < 4; i++) a[i] = As[ty * 4 + i][kk];
            #pragma unroll
            for (int j = 0; j < 4; j++) b[j] = Bs[kk][tx * 4 + j];
            #pragma unroll
            for (int i = 0; i < 4; i++)
                #pragma unroll
                for (int j = 0; j < 4; j++)
                    acc[i][j] += a[i] * b[j];
        }
        __syncthreads();
    }
    #pragma unroll
    for (int i = 0; i < 4; i++)
        #pragma unroll
        for (int j = 0; j < 4; j++) {
            size_t idx = (size_t)(row0 + ty * 4 + i) * Dq + col0 + tx * 4 + j;
            out[idx] = acc[i][j] + origin[idx];
        }
}

// ---------------------------------------------------------------------------
// Launch
// ---------------------------------------------------------------------------
extern "C" void kernel_launch(void* const* d_in, const int* in_sizes, int n_in,
                              void* d_out, int out_size)
{
    const float* input  = (const float*)d_in[0];
    // d_in[1] = encoder_output (unused by reference)
    const float* wq     = (const float*)d_in[2];
    const float* wk     = (const float*)d_in[3];
    const float* wv     = (const float*)d_in[4];
    const float* wo     = (const float*)d_in[5];
    const float* rel    = (const float*)d_in[6];
    const float* lnw    = (const float*)d_in[7];
    float* out          = (float*)d_out;

    // 66304 B dynamic smem for flash kernel (>48K default)
    static const int FLASH_SMEM = (2 * 64 * 65 + 64 * 64 + 64 * 65) * 4;
    cudaFuncSetAttribute(flash_kernel,
                         cudaFuncAttributeMaxDynamicSharedMemorySize, FLASH_SMEM);

    rms_kernel<<<Mq, 256>>>(input);

    dim3 gq(Dq / 64, Mq / 64, 3);
    gemm_qkv_kernel<<<gq, 256>>>(input, wq, wk, wv, lnw);

    dim3 gf(Sq / 64, Bq * Hq);
    flash_kernel<<<gf, 256, FLASH_SMEM>>>(rel);

    dim3 go(Dq / 64, Mq / 64);
    gemm_out_kernel<<<go, 256>>>(wo, input, out);
}

// round 3
// speedup vs baseline: 2.4787x; 2.4787x over previous
#include <cuda_runtime.h>
#include <cstdint>

#define Bq   4
#define Sq   2048
#define Dq   1024
#define Hq   16
#define HDq  64
#define Mq   (Bq*Sq)

__device__ float g_rscale[Mq];
__device__ float g_q[(size_t)Mq*Dq];
__device__ float g_k[(size_t)Mq*Dq];
__device__ float g_v[(size_t)Mq*Dq];
__device__ float g_ctx[(size_t)Mq*Dq];

// ---------------------------------------------------------------------------
// helpers
// ---------------------------------------------------------------------------
__device__ __forceinline__ uint32_t f2tf(float f) {
    uint32_t u;
    asm("cvt.rna.tf32.f32 %0, %1;" : "=r"(u) : "f"(f));
    return u;
}

__device__ __forceinline__ void mma8(float* c, const uint32_t* a, const uint32_t* b) {
    asm volatile(
        "mma.sync.aligned.m16n8k8.row.col.f32.tf32.tf32.f32 "
        "{%0,%1,%2,%3},{%4,%5,%6,%7},{%8,%9},{%0,%1,%2,%3};"
        : "+f"(c[0]), "+f"(c[1]), "+f"(c[2]), "+f"(c[3])
        : "r"(a[0]), "r"(a[1]), "r"(a[2]), "r"(a[3]), "r"(b[0]), "r"(b[1]));
}

__device__ __forceinline__ int rp_bucket(int rp) {
    if (rp < 0) rp = 0;
    if (rp < 16) return rp;
    int bk = 16 + (int)(__logf((float)rp * 0.0625f) * 7.6944086f);
    return bk > 31 ? 31 : bk;
}

// ---------------------------------------------------------------------------
// Kernel 1: RMS row scale
// ---------------------------------------------------------------------------
__global__ __launch_bounds__(256) void rms_kernel(const float* __restrict__ x) {
    int row = blockIdx.x;
    const float* xr = x + (size_t)row * Dq;
    float s = 0.f;
    for (int i = threadIdx.x; i < Dq; i += 256) {
        float v = xr[i];
        s += v * v;
    }
    __shared__ float red[8];
    #pragma unroll
    for (int o = 16; o > 0; o >>= 1) s += __shfl_xor_sync(0xffffffffu, s, o);
    if ((threadIdx.x & 31) == 0) red[threadIdx.x >> 5] = s;
    __syncthreads();
    if (threadIdx.x == 0) {
        float t = 0.f;
        #pragma unroll
        for (int i = 0; i < 8; i++) t += red[i];
        g_rscale[row] = rsqrtf(t * (1.0f / (float)Dq) + 1e-6f);
    }
}

// ---------------------------------------------------------------------------
// Kernel 2: tf32 tensor-core GEMM. C[M,1024] = A'[M,1024] @ W[1024,1024]
// NORM: A' = diag(rscale)*A*diag(lnw).  RES: C += res.
// BM=128 BN=128 BK=32, 256 threads, warp grid 2(M)x4(N), 4x4 m16n8 microtiles.
// ---------------------------------------------------------------------------
template<bool NORM, bool RES>
__global__ __launch_bounds__(256) void gemm_tc(
    const float* __restrict__ A, const float* __restrict__ W,
    float* __restrict__ C, const float* __restrict__ lnw,
    const float* __restrict__ res)
{
    __shared__ uint32_t As[128][36];   // 128 x 32 tile, stride 36 (conflict-free frag reads)
    __shared__ uint32_t Bs[32][136];   // 32 x 128 tile, stride 136

    const int tid = threadIdx.x;
    const int wid = tid >> 5, lane = tid & 31;
    const int lq = lane >> 2, lr = lane & 3;
    const int warpM = (wid & 1) * 64;
    const int warpN = (wid >> 1) * 32;
    const int row0 = blockIdx.y << 7, col0 = blockIdx.x << 7;

    float acc[4][4][4] = {};

    for (int k0 = 0; k0 < Dq; k0 += 32) {
        #pragma unroll
        for (int u = 0; u < 4; u++) {
            int lin = tid + u * 256;
            // A tile: 128 x 32
            int r = lin >> 3, c4 = (lin & 7) << 2;
            float4 av = *(const float4*)&A[(size_t)(row0 + r) * Dq + k0 + c4];
            if (NORM) {
                float rs = g_rscale[row0 + r];
                float4 lw = *(const float4*)&lnw[k0 + c4];
                av.x *= rs * lw.x; av.y *= rs * lw.y;
                av.z *= rs * lw.z; av.w *= rs * lw.w;
            }
            uint4 at = { f2tf(av.x), f2tf(av.y), f2tf(av.z), f2tf(av.w) };
            *(uint4*)&As[r][c4] = at;
            // B tile: 32 x 128
            int kr = lin >> 5, c4b = (lin & 31) << 2;
            float4 bv = *(const float4*)&W[(size_t)(k0 + kr) * Dq + col0 + c4b];
            uint4 bt = { f2tf(bv.x), f2tf(bv.y), f2tf(bv.z), f2tf(bv.w) };
            *(uint4*)&Bs[kr][c4b] = bt;
        }
        __syncthreads();

        #pragma unroll
        for (int ks = 0; ks < 4; ks++) {
            uint32_t a[4][4], b[4][2];
            #pragma unroll
            for (int mt = 0; mt < 4; mt++) {
                int rb = warpM + mt * 16 + lq;
                int cb = ks * 8 + lr;
                a[mt][0] = As[rb][cb];     a[mt][1] = As[rb + 8][cb];
                a[mt][2] = As[rb][cb + 4]; a[mt][3] = As[rb + 8][cb + 4];
            }
            #pragma unroll
            for (int nt = 0; nt < 4; nt++) {
                int nb = warpN + nt * 8 + lq;
                b[nt][0] = Bs[ks * 8 + lr][nb];
                b[nt][1] = Bs[ks * 8 + lr + 4][nb];
            }
            #pragma unroll
            for (int mt = 0; mt < 4; mt++)
                #pragma unroll
                for (int nt = 0; nt < 4; nt++)
                    mma8(acc[mt][nt], a[mt], b[nt]);
        }
        __syncthreads();
    }

    #pragma unroll
    for (int mt = 0; mt < 4; mt++)
        #pragma unroll
        for (int nt = 0; nt < 4; nt++) {
            int row = row0 + warpM + mt * 16 + lq;
            int col = col0 + warpN + nt * 8 + lr * 2;
            float2 v0 = { acc[mt][nt][0], acc[mt][nt][1] };
            float2 v1 = { acc[mt][nt][2], acc[mt][nt][3] };
            if (RES) {
                float2 r0 = *(const float2*)&res[(size_t)row * Dq + col];
                float2 r1 = *(const float2*)&res[(size_t)(row + 8) * Dq + col];
                v0.x += r0.x; v0.y += r0.y; v1.x += r1.x; v1.y += r1.y;
            }
            *(float2*)&C[(size_t)row * Dq + col] = v0;
            *(float2*)&C[(size_t)(row + 8) * Dq + col] = v1;
        }
}

// ---------------------------------------------------------------------------
// Kernel 3: flash attention, tf32 tensor cores.
// Block: 128 queries x one (b,h). 8 warps, each warp owns 16 full query rows.
// K-tiles of 64. smem strides: Q/P/K = 68, V = 72 (conflict-free frag reads).
// ---------------------------------------------------------------------------
#define QS(r, c) sm[(r) * 68 + (c)]
#define KS(r, c) sm[8704 + (r) * 68 + (c)]
#define VS(r, c) sm[13056 + (r) * 72 + (c)]
#define PS(r, c) sm[17664 + (r) * 68 + (c)]
#define FLASH_SMEM_WORDS (17664 + 128 * 68)

__global__ __launch_bounds__(256) void flash_tc(const float* __restrict__ rel_emb)
{
    extern __shared__ uint32_t sm[];
    __shared__ float bias_tab[32];

    const int tid = threadIdx.x;
    const int wid = tid >> 5, lane = tid & 31;
    const int lq = lane >> 2, lr = lane & 3;
    const int warpRow = wid * 16;

    const int q0 = blockIdx.x << 7;
    const int bh = blockIdx.y;
    const int b = bh >> 4, h = bh & 15;
    const size_t base = ((size_t)b * Sq) * Dq + (size_t)h * HDq;

    if (tid < 32) bias_tab[tid] = rel_emb[tid * Hq + h];

    // load Q tile (128 x 64) as tf32
    #pragma unroll
    for (int u = 0; u < 8; u++) {
        int lin = tid + u * 256;
        int r = lin >> 4, c4 = (lin & 15) << 2;
        float4 qv = *(const float4*)&g_q[base + (size_t)(q0 + r) * Dq + c4];
        uint4 qt = { f2tf(qv.x), f2tf(qv.y), f2tf(qv.z), f2tf(qv.w) };
        *(uint4*)&QS(r, c4) = qt;
    }

    const float NEG_INF = __int_as_float(0xff800000u);
    float mA = NEG_INF, mB = NEG_INF, lA = 0.f, lB = 0.f;
    float o[8][4] = {};
    const int rowA = q0 + warpRow + lq;

    for (int k0 = 0; k0 < Sq; k0 += 64) {
        __syncthreads();
        #pragma unroll
        for (int u = 0; u < 4; u++) {
            int lin = tid + u * 256;
            int r = lin >> 4, c4 = (lin & 15) << 2;
            float4 kv = *(const float4*)&g_k[base + (size_t)(k0 + r) * Dq + c4];
            uint4 kt = { f2tf(kv.x), f2tf(kv.y), f2tf(kv.z), f2tf(kv.w) };
            *(uint4*)&KS(r, c4) = kt;
            float4 vv = *(const float4*)&g_v[base + (size_t)(k0 + r) * Dq + c4];
            uint4 vt = { f2tf(vv.x), f2tf(vv.y), f2tf(vv.z), f2tf(vv.w) };
            *(uint4*)&VS(r, c4) = vt;
        }
        __syncthreads();

        // S = Q K^T  (warp rows x 64 keys)
        float s[8][4] = {};
        uint32_t aq[8][4];
        #pragma unroll
        for (int ks = 0; ks < 8; ks++) {
            int rb = warpRow + lq, cb = ks * 8 + lr;
            aq[ks][0] = QS(rb, cb);     aq[ks][1] = QS(rb + 8, cb);
            aq[ks][2] = QS(rb, cb + 4); aq[ks][3] = QS(rb + 8, cb + 4);
        }
        #pragma unroll
        for (int nt = 0; nt < 8; nt++) {
            #pragma unroll
            for (int ks = 0; ks < 8; ks++) {
                uint32_t bb[2];
                bb[0] = KS(nt * 8 + lq, ks * 8 + lr);
                bb[1] = KS(nt * 8 + lq, ks * 8 + lr + 4);
                mma8(s[nt], aq[ks], bb);
            }
        }

        // + relative position bias
        #pragma unroll
        for (int nt = 0; nt < 8; nt++) {
            int kc = k0 + nt * 8 + lr * 2;
            s[nt][0] += bias_tab[rp_bucket(rowA - kc)];
            s[nt][1] += bias_tab[rp_bucket(rowA - kc - 1)];
            s[nt][2] += bias_tab[rp_bucket(rowA + 8 - kc)];
            s[nt][3] += bias_tab[rp_bucket(rowA + 8 - kc - 1)];
        }

        // online softmax (rows A = lq, B = lq+8; reduce over quad lanes)
        float mxA = NEG_INF, mxB = NEG_INF;
        #pragma unroll
        for (int nt = 0; nt < 8; nt++) {
            mxA = fmaxf(mxA, fmaxf(s[nt][0], s[nt][1]));
            mxB = fmaxf(mxB, fmaxf(s[nt][2], s[nt][3]));
        }
        mxA = fmaxf(mxA, __shfl_xor_sync(0xffffffffu, mxA, 1));
        mxA = fmaxf(mxA, __shfl_xor_sync(0xffffffffu, mxA, 2));
        mxB = fmaxf(mxB, __shfl_xor_sync(0xffffffffu, mxB, 1));
        mxB = fmaxf(mxB, __shfl_xor_sync(0xffffffffu, mxB, 2));
        float nmA = fmaxf(mA, mxA), nmB = fmaxf(mB, mxB);
        float alA = __expf(mA - nmA), alB = __expf(mB - nmB);
        float sumA = 0.f, sumB = 0.f;
        #pragma unroll
        for (int nt = 0; nt < 8; nt++) {
            s[nt][0] = __expf(s[nt][0] - nmA); sumA += s[nt][0];
            s[nt][1] = __expf(s[nt][1] - nmA); sumA += s[nt][1];
            s[nt][2] = __expf(s[nt][2] - nmB); sumB += s[nt][2];
            s[nt][3] = __expf(s[nt][3] - nmB); sumB += s[nt][3];
        }
        sumA += __shfl_xor_sync(0xffffffffu, sumA, 1);
        sumA += __shfl_xor_sync(0xffffffffu, sumA, 2);
        sumB += __shfl_xor_sync(0xffffffffu, sumB, 1);
        sumB += __shfl_xor_sync(0xffffffffu, sumB, 2);
        lA = lA * alA + sumA; mA = nmA;
        lB = lB * alB + sumB; mB = nmB;
        #pragma unroll
        for (int nt = 0; nt < 8; nt++) {
            o[nt][0] *= alA; o[nt][1] *= alA;
            o[nt][2] *= alB; o[nt][3] *= alB;
        }

        // stage P (tf32) in warp-private smem, then PV mma
        #pragma unroll
        for (int nt = 0; nt < 8; nt++) {
            int c = nt * 8 + lr * 2;
            PS(warpRow + lq, c)     = f2tf(s[nt][0]);
            PS(warpRow + lq, c + 1) = f2tf(s[nt][1]);
            PS(warpRow + 8 + lq, c)     = f2tf(s[nt][2]);
            PS(warpRow + 8 + lq, c + 1) = f2tf(s[nt][3]);
        }
        __syncwarp();

        #pragma unroll
        for (int ks = 0; ks < 8; ks++) {
            uint32_t ap[4];
            int cb = ks * 8 + lr;
            ap[0] = PS(warpRow + lq, cb);     ap[1] = PS(warpRow + 8 + lq, cb);
            ap[2] = PS(warpRow + lq, cb + 4); ap[3] = PS(warpRow + 8 + lq, cb + 4);
            #pragma unroll
            for (int nt = 0; nt < 8; nt++) {
                uint32_t bb[2];
                bb[0] = VS(ks * 8 + lr, nt * 8 + lq);
                bb[1] = VS(ks * 8 + lr + 4, nt * 8 + lq);
                mma8(o[nt], ap, bb);
            }
        }
    }

    float invA = 1.0f / lA, invB = 1.0f / lB;
    #pragma unroll
    for (int nt = 0; nt < 8; nt++) {
        int col = nt * 8 + lr * 2;
        float2 vA = { o[nt][0] * invA, o[nt][1] * invA };
        float2 vB = { o[nt][2] * invB, o[nt][3] * invB };
        *(float2*)&g_ctx[base + (size_t)rowA * Dq + col] = vA;
        *(float2*)&g_ctx[base + (size_t)(rowA + 8) * Dq + col] = vB;
    }
}

// ---------------------------------------------------------------------------
// Launch
// ---------------------------------------------------------------------------
extern "C" void kernel_launch(void* const* d_in, const int* in_sizes, int n_in,
                              void* d_out, int out_size)
{
    const float* input = (const float*)d_in[0];
    const float* wq    = (const float*)d_in[2];
    const float* wk    = (const float*)d_in[3];
    const float* wv    = (const float*)d_in[4];
    const float* wo    = (const float*)d_in[5];
    const float* rel   = (const float*)d_in[6];
    const float* lnw   = (const float*)d_in[7];
    float* out         = (float*)d_out;

    static const int FLASH_SMEM = FLASH_SMEM_WORDS * 4;  // 105472 B
    cudaFuncSetAttribute(flash_tc,
                         cudaFuncAttributeMaxDynamicSharedMemorySize, FLASH_SMEM);

    rms_kernel<<<Mq, 256>>>(input);

    dim3 gg(Dq / 128, Mq / 128);
    float* g_q_p;  cudaGetSymbolAddress((void**)&g_q_p, g_q);
    float* g_k_p;  cudaGetSymbolAddress((void**)&g_k_p, g_k);
    float* g_v_p;  cudaGetSymbolAddress((void**)&g_v_p, g_v);
    float* g_ctx_p; cudaGetSymbolAddress((void**)&g_ctx_p, g_ctx);

    gemm_tc<true, false><<<gg, 256>>>(input, wq, g_q_p, lnw, nullptr);
    gemm_tc<true, false><<<gg, 256>>>(input, wk, g_k_p, lnw, nullptr);
    gemm_tc<true, false><<<gg, 256>>>(input, wv, g_v_p, lnw, nullptr);

    dim3 gf(Sq / 128, Bq * Hq);
    flash_tc<<<gf, 256, FLASH_SMEM>>>(rel);

    gemm_tc<false, true><<<gg, 256>>>(g_ctx_p, wo, out, nullptr, input);
}

// round 4
// speedup vs baseline: 3.3670x; 1.3584x over previous
#include <cuda_runtime.h>
#include <cstdint>

#define Bq   4
#define Sq   2048
#define Dq   1024
#define Hq   16
#define HDq  64
#define Mq   (Bq*Sq)

__device__ float g_xn[(size_t)Mq*Dq];   // normalized input
__device__ float g_q[(size_t)Mq*Dq];
__device__ float g_k[(size_t)Mq*Dq];
__device__ float g_v[(size_t)Mq*Dq];
__device__ float g_ctx[(size_t)Mq*Dq];

// ---------------------------------------------------------------------------
// helpers
// ---------------------------------------------------------------------------
__device__ __forceinline__ uint32_t f2tf(float f) {
    uint32_t u;
    asm("cvt.rna.tf32.f32 %0, %1;" : "=r"(u) : "f"(f));
    return u;
}

__device__ __forceinline__ void mma8(float* c, const uint32_t* a, const uint32_t* b) {
    asm volatile(
        "mma.sync.aligned.m16n8k8.row.col.f32.tf32.tf32.f32 "
        "{%0,%1,%2,%3},{%4,%5,%6,%7},{%8,%9},{%0,%1,%2,%3};"
        : "+f"(c[0]), "+f"(c[1]), "+f"(c[2]), "+f"(c[3])
        : "r"(a[0]), "r"(a[1]), "r"(a[2]), "r"(a[3]), "r"(b[0]), "r"(b[1]));
}

__device__ __forceinline__ void cp16(uint32_t dst, const void* src) {
    asm volatile("cp.async.cg.shared.global [%0], [%1], 16;"
                 :: "r"(dst), "l"(src));
}
__device__ __forceinline__ void cp_commit() {
    asm volatile("cp.async.commit_group;");
}
__device__ __forceinline__ void cp_wait0() {
    asm volatile("cp.async.wait_group 0;");
}

__device__ __forceinline__ int rp_bucket(int rp) {
    if (rp < 0) rp = 0;
    if (rp < 16) return rp;
    int bk = 16 + (int)(__logf((float)rp * 0.0625f) * 7.6944086f);
    return bk > 31 ? 31 : bk;
}

// ---------------------------------------------------------------------------
// Kernel 1: fused RMS norm: xn = x * rsqrt(mean(x^2)+eps) * lnw
// ---------------------------------------------------------------------------
__global__ __launch_bounds__(256) void norm_kernel(
    const float* __restrict__ x, const float* __restrict__ lnw,
    float* __restrict__ xn)
{
    int row = blockIdx.x;
    const float4* xr = (const float4*)(x + (size_t)row * Dq);
    float4 v = xr[threadIdx.x];
    float s = v.x * v.x + v.y * v.y + v.z * v.z + v.w * v.w;
    __shared__ float red[8];
    #pragma unroll
    for (int o = 16; o > 0; o >>= 1) s += __shfl_xor_sync(0xffffffffu, s, o);
    if ((threadIdx.x & 31) == 0) red[threadIdx.x >> 5] = s;
    __syncthreads();
    float t = 0.f;
    #pragma unroll
    for (int i = 0; i < 8; i++) t += red[i];
    float rs = rsqrtf(t * (1.0f / (float)Dq) + 1e-6f);
    float4 lw = ((const float4*)lnw)[threadIdx.x];
    float4 o4 = { v.x * rs * lw.x, v.y * rs * lw.y,
                  v.z * rs * lw.z, v.w * rs * lw.w };
    ((float4*)(xn + (size_t)row * Dq))[threadIdx.x] = o4;
}

// ---------------------------------------------------------------------------
// Kernel 2: tf32 tensor-core GEMM with cp.async 2-stage double buffering.
// BM=BN=128, BK=32, 256 threads, 2 CTAs/SM, warp grid 2(M)x4(N), 4x4 m16n8.
// QKV=true: blockIdx.x selects among {wq,wk,wv} (grid.x = 24).
// RES=true: C = A@W + res.
// smem words: A 2x128x36 = 9216, B 2x32x136 = 8704 -> 71680 B.
// ---------------------------------------------------------------------------
#define GA_ST   36
#define GB_ST   136
#define GA_WORDS (128 * GA_ST)          // 4608 per stage
#define GB_WORDS (32 * GB_ST)           // 4352 per stage
#define GB_BASE  (2 * GA_WORDS)         // 9216
#define GEMM_SMEM_BYTES ((2 * GA_WORDS + 2 * GB_WORDS) * 4)  // 71680

template<bool QKV, bool RES>
__global__ __launch_bounds__(256, 2) void gemm_tc2(
    const float* __restrict__ A,
    const float* __restrict__ W0, const float* __restrict__ W1,
    const float* __restrict__ W2,
    float* __restrict__ C0, float* __restrict__ C1, float* __restrict__ C2,
    const float* __restrict__ res)
{
    extern __shared__ float smf[];
    uint32_t smb = (uint32_t)__cvta_generic_to_shared(smf);

    const float* W;
    float* C;
    int col0;
    if (QKV) {
        int which = blockIdx.x >> 3;
        W = (which == 0) ? W0 : (which == 1) ? W1 : W2;
        C = (which == 0) ? C0 : (which == 1) ? C1 : C2;
        col0 = (blockIdx.x & 7) << 7;
    } else {
        W = W0; C = C0;
        col0 = blockIdx.x << 7;
    }
    const int row0 = blockIdx.y << 7;

    const int tid = threadIdx.x;
    const int wid = tid >> 5, lane = tid & 31;
    const int lq = lane >> 2, lr = lane & 3;
    const int warpM = (wid & 1) * 64;
    const int warpN = (wid >> 1) * 32;

    // copy-index precompute
    const int ar = tid >> 3, ac = (tid & 7) << 2;        // A: 2 rows-chunks /u
    const int br = tid >> 5, bc = (tid & 31) << 2;       // B

    auto copyA = [&](int k0, int st) {
        #pragma unroll
        for (int u = 0; u < 4; u++) {
            int r = ar + u * 32;
            uint32_t dst = smb + (st * GA_WORDS + r * GA_ST + ac) * 4;
            cp16(dst, A + (size_t)(row0 + r) * Dq + k0 + ac);
        }
    };
    auto copyB = [&](int k0, int st) {
        #pragma unroll
        for (int u = 0; u < 4; u++) {
            int r = br + u * 8;
            uint32_t dst = smb + (GB_BASE + st * GB_WORDS + r * GB_ST + bc) * 4;
            cp16(dst, W + (size_t)(k0 + r) * Dq + col0 + bc);
        }
    };

    float acc[4][4][4] = {};

    copyA(0, 0); copyB(0, 0); cp_commit();

    int stage = 0;
    for (int k0 = 0; k0 < Dq; k0 += 32, stage ^= 1) {
        cp_wait0();
        __syncthreads();
        if (k0 + 32 < Dq) {
            copyA(k0 + 32, stage ^ 1);
            copyB(k0 + 32, stage ^ 1);
            cp_commit();
        }
        const float* As = smf + stage * GA_WORDS;
        const float* Bs = smf + GB_BASE + stage * GB_WORDS;

        #pragma unroll
        for (int ks = 0; ks < 4; ks++) {
            uint32_t a[4][4], b[4][2];
            #pragma unroll
            for (int mt = 0; mt < 4; mt++) {
                int rb = warpM + mt * 16 + lq;
                int cb = ks * 8 + lr;
                a[mt][0] = f2tf(As[rb * GA_ST + cb]);
                a[mt][1] = f2tf(As[(rb + 8) * GA_ST + cb]);
                a[mt][2] = f2tf(As[rb * GA_ST + cb + 4]);
                a[mt][3] = f2tf(As[(rb + 8) * GA_ST + cb + 4]);
            }
            #pragma unroll
            for (int nt = 0; nt < 4; nt++) {
                int nb = warpN + nt * 8 + lq;
                b[nt][0] = f2tf(Bs[(ks * 8 + lr) * GB_ST + nb]);
                b[nt][1] = f2tf(Bs[(ks * 8 + lr + 4) * GB_ST + nb]);
            }
            #pragma unroll
            for (int mt = 0; mt < 4; mt++)
                #pragma unroll
                for (int nt = 0; nt < 4; nt++)
                    mma8(acc[mt][nt], a[mt], b[nt]);
        }
    }

    #pragma unroll
    for (int mt = 0; mt < 4; mt++)
        #pragma unroll
        for (int nt = 0; nt < 4; nt++) {
            int row = row0 + warpM + mt * 16 + lq;
            int col = col0 + warpN + nt * 8 + lr * 2;
            float2 v0 = { acc[mt][nt][0], acc[mt][nt][1] };
            float2 v1 = { acc[mt][nt][2], acc[mt][nt][3] };
            if (RES) {
                float2 r0 = *(const float2*)&res[(size_t)row * Dq + col];
                float2 r1 = *(const float2*)&res[(size_t)(row + 8) * Dq + col];
                v0.x += r0.x; v0.y += r0.y; v1.x += r1.x; v1.y += r1.y;
            }
            *(float2*)&C[(size_t)row * Dq + col] = v0;
            *(float2*)&C[(size_t)(row + 8) * Dq + col] = v1;
        }
}

// ---------------------------------------------------------------------------
// Kernel 3: flash attention, tf32 tensor cores (unchanged from R3).
// ---------------------------------------------------------------------------
#define QS(r, c) sm[(r) * 68 + (c)]
#define KS(r, c) sm[8704 + (r) * 68 + (c)]
#define VS(r, c) sm[13056 + (r) * 72 + (c)]
#define PS(r, c) sm[17664 + (r) * 68 + (c)]
#define FLASH_SMEM_WORDS (17664 + 128 * 68)

__global__ __launch_bounds__(256) void flash_tc(const float* __restrict__ rel_emb)
{
    extern __shared__ uint32_t sm[];
    __shared__ float bias_tab[32];

    const int tid = threadIdx.x;
    const int wid = tid >> 5, lane = tid & 31;
    const int lq = lane >> 2, lr = lane & 3;
    const int warpRow = wid * 16;

    const int q0 = blockIdx.x << 7;
    const int bh = blockIdx.y;
    const int b = bh >> 4, h = bh & 15;
    const size_t base = ((size_t)b * Sq) * Dq + (size_t)h * HDq;

    if (tid < 32) bias_tab[tid] = rel_emb[tid * Hq + h];

    #pragma unroll
    for (int u = 0; u < 8; u++) {
        int lin = tid + u * 256;
        int r = lin >> 4, c4 = (lin & 15) << 2;
        float4 qv = *(const float4*)&g_q[base + (size_t)(q0 + r) * Dq + c4];
        uint4 qt = { f2tf(qv.x), f2tf(qv.y), f2tf(qv.z), f2tf(qv.w) };
        *(uint4*)&QS(r, c4) = qt;
    }

    const float NEG_INF = __int_as_float(0xff800000u);
    float mA = NEG_INF, mB = NEG_INF, lA = 0.f, lB = 0.f;
    float o[8][4] = {};
    const int rowA = q0 + warpRow + lq;

    for (int k0 = 0; k0 < Sq; k0 += 64) {
        __syncthreads();
        #pragma unroll
        for (int u = 0; u < 4; u++) {
            int lin = tid + u * 256;
            int r = lin >> 4, c4 = (lin & 15) << 2;
            float4 kv = *(const float4*)&g_k[base + (size_t)(k0 + r) * Dq + c4];
            uint4 kt = { f2tf(kv.x), f2tf(kv.y), f2tf(kv.z), f2tf(kv.w) };
            *(uint4*)&KS(r, c4) = kt;
            float4 vv = *(const float4*)&g_v[base + (size_t)(k0 + r) * Dq + c4];
            uint4 vt = { f2tf(vv.x), f2tf(vv.y), f2tf(vv.z), f2tf(vv.w) };
            *(uint4*)&VS(r, c4) = vt;
        }
        __syncthreads();

        float s[8][4] = {};
        uint32_t aq[8][4];
        #pragma unroll
        for (int ks = 0; ks < 8; ks++) {
            int rb = warpRow + lq, cb = ks * 8 + lr;
            aq[ks][0] = QS(rb, cb);     aq[ks][1] = QS(rb + 8, cb);
            aq[ks][2] = QS(rb, cb + 4); aq[ks][3] = QS(rb + 8, cb + 4);
        }
        #pragma unroll
        for (int nt = 0; nt < 8; nt++) {
            #pragma unroll
            for (int ks = 0; ks < 8; ks++) {
                uint32_t bb[2];
                bb[0] = KS(nt * 8 + lq, ks * 8 + lr);
                bb[1] = KS(nt * 8 + lq, ks * 8 + lr + 4);
                mma8(s[nt], aq[ks], bb);
            }
        }

        #pragma unroll
        for (int nt = 0; nt < 8; nt++) {
            int kc = k0 + nt * 8 + lr * 2;
            s[nt][0] += bias_tab[rp_bucket(rowA - kc)];
            s[nt][1] += bias_tab[rp_bucket(rowA - kc - 1)];
            s[nt][2] += bias_tab[rp_bucket(rowA + 8 - kc)];
            s[nt][3] += bias_tab[rp_bucket(rowA + 8 - kc - 1)];
        }

        float mxA = NEG_INF, mxB = NEG_INF;
        #pragma unroll
        for (int nt = 0; nt < 8; nt++) {
            mxA = fmaxf(mxA, fmaxf(s[nt][0], s[nt][1]));
            mxB = fmaxf(mxB, fmaxf(s[nt][2], s[nt][3]));
        }
        mxA = fmaxf(mxA, __shfl_xor_sync(0xffffffffu, mxA, 1));
        mxA = fmaxf(mxA, __shfl_xor_sync(0xffffffffu, mxA, 2));
        mxB = fmaxf(mxB, __shfl_xor_sync(0xffffffffu, mxB, 1));
        mxB = fmaxf(mxB, __shfl_xor_sync(0xffffffffu, mxB, 2));
        float nmA = fmaxf(mA, mxA), nmB = fmaxf(mB, mxB);
        float alA = __expf(mA - nmA), alB = __expf(mB - nmB);
        float sumA = 0.f, sumB = 0.f;
        #pragma unroll
        for (int nt = 0; nt < 8; nt++) {
            s[nt][0] = __expf(s[nt][0] - nmA); sumA += s[nt][0];
            s[nt][1] = __expf(s[nt][1] - nmA); sumA += s[nt][1];
            s[nt][2] = __expf(s[nt][2] - nmB); sumB += s[nt][2];
            s[nt][3] = __expf(s[nt][3] - nmB); sumB += s[nt][3];
        }
        sumA += __shfl_xor_sync(0xffffffffu, sumA, 1);
        sumA += __shfl_xor_sync(0xffffffffu, sumA, 2);
        sumB += __shfl_xor_sync(0xffffffffu, sumB, 1);
        sumB += __shfl_xor_sync(0xffffffffu, sumB, 2);
        lA = lA * alA + sumA; mA = nmA;
        lB = lB * alB + sumB; mB = nmB;
        #pragma unroll
        for (int nt = 0; nt < 8; nt++) {
            o[nt][0] *= alA; o[nt][1] *= alA;
            o[nt][2] *= alB; o[nt][3] *= alB;
        }

        #pragma unroll
        for (int nt = 0; nt < 8; nt++) {
            int c = nt * 8 + lr * 2;
            PS(warpRow + lq, c)     = f2tf(s[nt][0]);
            PS(warpRow + lq, c + 1) = f2tf(s[nt][1]);
            PS(warpRow + 8 + lq, c)     = f2tf(s[nt][2]);
            PS(warpRow + 8 + lq, c + 1) = f2tf(s[nt][3]);
        }
        __syncwarp();

        #pragma unroll
        for (int ks = 0; ks < 8; ks++) {
            uint32_t ap[4];
            int cb = ks * 8 + lr;
            ap[0] = PS(warpRow + lq, cb);     ap[1] = PS(warpRow + 8 + lq, cb);
            ap[2] = PS(warpRow + lq, cb + 4); ap[3] = PS(warpRow + 8 + lq, cb + 4);
            #pragma unroll
            for (int nt = 0; nt < 8; nt++) {
                uint32_t bb[2];
                bb[0] = VS(ks * 8 + lr, nt * 8 + lq);
                bb[1] = VS(ks * 8 + lr + 4, nt * 8 + lq);
                mma8(o[nt], ap, bb);
            }
        }
    }

    float invA = 1.0f / lA, invB = 1.0f / lB;
    #pragma unroll
    for (int nt = 0; nt < 8; nt++) {
        int col = nt * 8 + lr * 2;
        float2 vA = { o[nt][0] * invA, o[nt][1] * invA };
        float2 vB = { o[nt][2] * invB, o[nt][3] * invB };
        *(float2*)&g_ctx[base + (size_t)rowA * Dq + col] = vA;
        *(float2*)&g_ctx[base + (size_t)(rowA + 8) * Dq + col] = vB;
    }
}

// ---------------------------------------------------------------------------
// Launch
// ---------------------------------------------------------------------------
extern "C" void kernel_launch(void* const* d_in, const int* in_sizes, int n_in,
                              void* d_out, int out_size)
{
    const float* input = (const float*)d_in[0];
    const float* wq    = (const float*)d_in[2];
    const float* wk    = (const float*)d_in[3];
    const float* wv    = (const float*)d_in[4];
    const float* wo    = (const float*)d_in[5];
    const float* rel   = (const float*)d_in[6];
    const float* lnw   = (const float*)d_in[7];
    float* out         = (float*)d_out;

    static const int FLASH_SMEM = FLASH_SMEM_WORDS * 4;
    cudaFuncSetAttribute(flash_tc,
                         cudaFuncAttributeMaxDynamicSharedMemorySize, FLASH_SMEM);
    cudaFuncSetAttribute(gemm_tc2<true, false>,
                         cudaFuncAttributeMaxDynamicSharedMemorySize, GEMM_SMEM_BYTES);
    cudaFuncSetAttribute(gemm_tc2<false, true>,
                         cudaFuncAttributeMaxDynamicSharedMemorySize, GEMM_SMEM_BYTES);

    float *g_xn_p, *g_q_p, *g_k_p, *g_v_p, *g_ctx_p;
    cudaGetSymbolAddress((void**)&g_xn_p, g_xn);
    cudaGetSymbolAddress((void**)&g_q_p,  g_q);
    cudaGetSymbolAddress((void**)&g_k_p,  g_k);
    cudaGetSymbolAddress((void**)&g_v_p,  g_v);
    cudaGetSymbolAddress((void**)&g_ctx_p, g_ctx);

    norm_kernel<<<Mq, 256>>>(input, lnw, g_xn_p);

    dim3 gqkv(24, Mq / 128);
    gemm_tc2<true, false><<<gqkv, 256, GEMM_SMEM_BYTES>>>(
        g_xn_p, wq, wk, wv, g_q_p, g_k_p, g_v_p, nullptr);

    dim3 gf(Sq / 128, Bq * Hq);
    flash_tc<<<gf, 256, FLASH_SMEM>>>(rel);

    dim3 go(Dq / 128, Mq / 128);
    gemm_tc2<false, true><<<go, 256, GEMM_SMEM_BYTES>>>(
        g_ctx_p, wo, nullptr, nullptr, out, nullptr, nullptr, input);
}